// round 1
// baseline (speedup 1.0000x reference)
#include <cuda_runtime.h>

// PANNAcceptor: out[b] = lin_w @ (W[x_{L-1}] ... W[x_0] @ e0) + lin_b
// Inputs (metadata order): xs[int32 B*S], lengths[int32 B], W[f32 A*N*N],
//                          lin_w[f32 2*N], lin_b[f32 2]. Output: f32 [B,2].
//
// Baseline strategy: one CTA per batch, stream W[x_t] from L2 each step,
// h ping-pong in shared memory, fp32 FFMA + shfl reduction.

#define NST 256          // number of states (compile-time: layout depends on it)
#define THREADS 512      // 16 warps; each warp owns 16 output rows

__global__ __launch_bounds__(THREADS, 1)
void pann_chain_kernel(const int* __restrict__ xs,
                       const int* __restrict__ lengths,
                       const float* __restrict__ W,
                       const float* __restrict__ lin_w,
                       const float* __restrict__ lin_b,
                       float* __restrict__ out,
                       int S)
{
    __shared__ float hbuf[2][NST];

    const int b    = blockIdx.x;
    const int tid  = threadIdx.x;
    const int warp = tid >> 5;
    const int lane = tid & 31;

    // h0 = one-hot(state 0)
    if (tid < NST) hbuf[0][tid] = (tid == 0) ? 1.0f : 0.0f;

    const int L = lengths[b];
    const int* xrow = xs + (size_t)b * S;
    __syncthreads();

    int cur = 0;
    const int i0 = warp * 16;   // this warp's 16 output rows

    for (int t = 0; t < L; ++t) {
        const int a = __ldg(xrow + t);
        const float* Wa = W + (size_t)a * (NST * NST);
        const float* hsrc = hbuf[cur];
        float* hdst = hbuf[cur ^ 1];

        // This lane's column slice of h: cols [4*lane, 4*lane+4) and [128+4*lane, ...)
        const float4 hA = *(const float4*)(hsrc + lane * 4);
        const float4 hB = *(const float4*)(hsrc + 128 + lane * 4);

        #pragma unroll 4
        for (int r = 0; r < 16; ++r) {
            const int i = i0 + r;
            const float4* p = (const float4*)(Wa + (size_t)i * NST + lane * 4);
            const float4 wA = p[0];    // cols [4*lane, 4*lane+4)          (contiguous 512B/warp)
            const float4 wB = p[32];   // cols [128+4*lane, 128+4*lane+4)  (contiguous 512B/warp)

            float s = wA.x * hA.x + wA.y * hA.y + wA.z * hA.z + wA.w * hA.w
                    + wB.x * hB.x + wB.y * hB.y + wB.z * hB.z + wB.w * hB.w;

            // 32-lane tree reduce
            s += __shfl_xor_sync(0xffffffffu, s, 16);
            s += __shfl_xor_sync(0xffffffffu, s, 8);
            s += __shfl_xor_sync(0xffffffffu, s, 4);
            s += __shfl_xor_sync(0xffffffffu, s, 2);
            s += __shfl_xor_sync(0xffffffffu, s, 1);
            if (lane == 0) hdst[i] = s;
        }
        __syncthreads();
        cur ^= 1;
    }

    // Linear head: out[b][k] = sum_i lin_w[k][i] * h[i] + lin_b[k]
    const float* hf = hbuf[cur];
    if (warp < 2) {
        const int k = warp;
        float s = 0.0f;
        #pragma unroll
        for (int i = lane; i < NST; i += 32)
            s += lin_w[k * NST + i] * hf[i];
        s += __shfl_xor_sync(0xffffffffu, s, 16);
        s += __shfl_xor_sync(0xffffffffu, s, 8);
        s += __shfl_xor_sync(0xffffffffu, s, 4);
        s += __shfl_xor_sync(0xffffffffu, s, 2);
        s += __shfl_xor_sync(0xffffffffu, s, 1);
        if (lane == 0) out[b * 2 + k] = s + lin_b[k];
    }
}

extern "C" void kernel_launch(void* const* d_in, const int* in_sizes, int n_in,
                              void* d_out, int out_size)
{
    const int*   xs      = (const int*)d_in[0];
    const int*   lengths = (const int*)d_in[1];
    const float* W       = (const float*)d_in[2];
    const float* lin_w   = (const float*)d_in[3];
    const float* lin_b   = (const float*)d_in[4];
    float*       out     = (float*)d_out;

    const int B = in_sizes[1];          // number of batches (lengths count)
    const int S = in_sizes[0] / B;      // max sequence length

    pann_chain_kernel<<<B, THREADS>>>(xs, lengths, W, lin_w, lin_b, out, S);
}